// round 6
// baseline (speedup 1.0000x reference)
#include <cuda_runtime.h>

#define N_NODES   100000
#define E_EDGES   1600000
#define H_DIM     128
#define L_LAYERS  4
#define C_CLASSES 12
#define G_GRAPHS  512
#define BN_EPS    1e-5f

#define SCAN_T    1024
#define CHUNK     ((N_NODES + SCAN_T - 1) / SCAN_T)   // 98

// f32x2 packed helpers
#define PACK_DUP(d, x) asm("mov.b64 %0, {%1, %1};" : "=l"(d) : "r"(__float_as_uint(x)))
#define FMA2(d, a, b, c) asm("fma.rn.f32x2 %0, %1, %2, %3;" : "=l"(d) : "l"(a), "l"(b), "l"(c))
#define UNPACK2(lo, hi, p) asm("mov.b64 {%0, %1}, %2;" : "=f"(lo), "=f"(hi) : "l"(p))

// ---------------- device scratch (no allocation allowed) ----------------
__device__ __align__(128) float g_h  [N_NODES * H_DIM];   // activations
__device__ __align__(128) float g_hw [N_NODES * H_DIM];   // (h @ W) * dinv[row]
__device__ __align__(128) float g_dinv[N_NODES];
__device__ __align__(128) int   g_deg [N_NODES];
__device__ __align__(128) int   g_rowstart[N_NODES + 1];
__device__ __align__(128) int   g_cursor  [N_NODES];
__device__ __align__(128) int   g_csr_src [E_EDGES];
__device__ __align__(128) float g_pool[G_GRAPHS * H_DIM];
__device__ __align__(128) int   g_cnt [G_GRAPHS];

// ---------------- zero / degree / dinv ----------------
__global__ void zero_kernel() {
    int i = blockIdx.x * blockDim.x + threadIdx.x;
    if (i < N_NODES)          g_deg[i] = 0;
    if (i < G_GRAPHS * H_DIM) g_pool[i] = 0.f;
    if (i < G_GRAPHS)         g_cnt[i] = 0;
}

__global__ void degree_kernel(const int* __restrict__ ei) {
    int e = blockIdx.x * blockDim.x + threadIdx.x;
    if (e < E_EDGES) atomicAdd(&g_deg[ei[E_EDGES + e]], 1);
}

// single-block exclusive scan of g_deg -> g_rowstart / g_cursor, plus dinv
__global__ void __launch_bounds__(SCAN_T) scan_kernel() {
    __shared__ int part[SCAN_T];
    int t  = threadIdx.x;
    int lo = t * CHUNK;
    int hi = min(lo + CHUNK, N_NODES);
    int s = 0;
    for (int i = lo; i < hi; i++) s += g_deg[i];
    part[t] = s;
    __syncthreads();
    for (int d = 1; d < SCAN_T; d <<= 1) {
        int v = (t >= d) ? part[t - d] : 0;
        __syncthreads();
        part[t] += v;
        __syncthreads();
    }
    int run = part[t] - s;
    for (int i = lo; i < hi; i++) {
        g_rowstart[i] = run;
        g_cursor[i]   = run;
        int dg = g_deg[i];
        g_dinv[i] = rsqrtf((float)dg + 1.0f);
        run += dg;
    }
    if (t == SCAN_T - 1) g_rowstart[N_NODES] = run;
}

__global__ void fill_csr_kernel(const int* __restrict__ ei) {
    int e = blockIdx.x * blockDim.x + threadIdx.x;
    if (e < E_EDGES) {
        int s = ei[e];
        int d = ei[E_EDGES + e];
        int pos = atomicAdd(&g_cursor[d], 1);
        g_csr_src[pos] = s;
    }
}

// ---------------- GEMM (FFMA2): [N,128] @ [128,128] ----------------
// mode 0: g_h  = relu(x @ W + bias)          (A = x param)
// mode 1: g_hw = (g_h @ W) * dinv[row]
__global__ void __launch_bounds__(256) gemm_kernel(
    const float* __restrict__ A_in, const float* __restrict__ W,
    const float* __restrict__ bias, int mode)
{
    extern __shared__ float sm[];
    float* Ws = sm;                                            // [128][128] f32
    unsigned long long* As2 = (unsigned long long*)(sm + 128 * 128); // [64][128] {a,a}

    const float* A = (mode == 0) ? A_in : g_h;
    int tid  = threadIdx.x;
    int row0 = blockIdx.x * 64;

    // load W tile (16384 floats, coalesced float4)
    const float4* W4 = (const float4*)W;
    float4* Ws4 = (float4*)Ws;
#pragma unroll
    for (int i = 0; i < 16; i++) Ws4[tid + 256 * i] = W4[tid + 256 * i];

    // load A tile (64 rows x 128) duplicated into f32x2 pairs
#pragma unroll
    for (int i = 0; i < 8; i++) {
        int idx = tid + 256 * i;          // float4 index, 32 per row
        int r   = idx >> 5;
        int c   = idx & 31;
        float4 v = make_float4(0.f, 0.f, 0.f, 0.f);
        if (row0 + r < N_NODES)
            v = ((const float4*)(A + (size_t)(row0 + r) * 128))[c];
        unsigned long long* dst = As2 + r * 128 + c * 4;
        unsigned long long p0, p1, p2, p3;
        PACK_DUP(p0, v.x); PACK_DUP(p1, v.y); PACK_DUP(p2, v.z); PACK_DUP(p3, v.w);
        dst[0] = p0; dst[1] = p1; dst[2] = p2; dst[3] = p3;
    }
    __syncthreads();

    int warp = tid >> 5, lane = tid & 31;
    unsigned long long acc2[8][2];
#pragma unroll
    for (int r = 0; r < 8; r++) { acc2[r][0] = 0ull; acc2[r][1] = 0ull; }

    const unsigned long long* A2row = As2 + warp * 8 * 128;
#pragma unroll 4
    for (int k = 0; k < 128; k++) {
        ulonglong2 w2 = ((const ulonglong2*)(Ws + k * 128))[lane];  // cols 4*lane..+3
#pragma unroll
        for (int r = 0; r < 8; r++) {
            unsigned long long a2 = A2row[r * 128 + k];
            FMA2(acc2[r][0], a2, w2.x, acc2[r][0]);
            FMA2(acc2[r][1], a2, w2.y, acc2[r][1]);
        }
    }

    if (mode == 0) {
        float4 bv = ((const float4*)bias)[lane];
#pragma unroll
        for (int r = 0; r < 8; r++) {
            int row = row0 + warp * 8 + r;
            if (row < N_NODES) {
                float a0, a1, a2v, a3;
                UNPACK2(a0, a1, acc2[r][0]);
                UNPACK2(a2v, a3, acc2[r][1]);
                float4 o;
                o.x = fmaxf(a0  + bv.x, 0.f);
                o.y = fmaxf(a1  + bv.y, 0.f);
                o.z = fmaxf(a2v + bv.z, 0.f);
                o.w = fmaxf(a3  + bv.w, 0.f);
                ((float4*)(g_h + (size_t)row * 128))[lane] = o;
            }
        }
    } else {
#pragma unroll
        for (int r = 0; r < 8; r++) {
            int row = row0 + warp * 8 + r;
            if (row < N_NODES) {
                float dv = g_dinv[row];
                float a0, a1, a2v, a3;
                UNPACK2(a0, a1, acc2[r][0]);
                UNPACK2(a2v, a3, acc2[r][1]);
                float4 o;
                o.x = a0  * dv;
                o.y = a1  * dv;
                o.z = a2v * dv;
                o.w = a3  * dv;
                ((float4*)(g_hw + (size_t)row * 128))[lane] = o;
            }
        }
    }
}

// ---------------- fused aggregation + BN + ReLU (warp per dst node) ----------------
// h[n] = relu( BN( ( g_hw[n] + sum_{src->n} g_hw[src] ) * dinv[n] + conv_b ) )
// last=1: additionally reduce into g_pool[batch[n]] and skip the g_h store.
__global__ void __launch_bounds__(256) agg_kernel(
    const float* __restrict__ cb,
    const float* __restrict__ gamma,
    const float* __restrict__ beta,
    const float* __restrict__ mean,
    const float* __restrict__ var,
    const int* __restrict__ batch, int last)
{
    unsigned gtid = blockIdx.x * blockDim.x + threadIdx.x;
    unsigned n    = gtid >> 5;
    int lane      = threadIdx.x & 31;
    if (n >= N_NODES) return;

    float4 acc = ((const float4*)(g_hw + (size_t)n * 128))[lane];   // self term

    int start = g_rowstart[n];
    int end   = g_rowstart[n + 1];
    for (int base = start; base < end; base += 32) {
        int cnt = min(32, end - base);
        int src = (base + lane < end) ? g_csr_src[base + lane] : 0;
#pragma unroll 4
        for (int j = 0; j < cnt; j++) {
            int s = __shfl_sync(0xffffffffu, src, j);
            float4 v = __ldg((const float4*)(g_hw + (size_t)s * 128) + lane);
            acc.x += v.x; acc.y += v.y; acc.z += v.z; acc.w += v.w;
        }
    }

    float dv = g_dinv[n];
    int c4   = lane * 4;
    float4 o;
    {
        float s = gamma[c4 + 0] * rsqrtf(var[c4 + 0] + BN_EPS);
        o.x = fmaxf((acc.x * dv + cb[c4 + 0] - mean[c4 + 0]) * s + beta[c4 + 0], 0.f);
        s = gamma[c4 + 1] * rsqrtf(var[c4 + 1] + BN_EPS);
        o.y = fmaxf((acc.y * dv + cb[c4 + 1] - mean[c4 + 1]) * s + beta[c4 + 1], 0.f);
        s = gamma[c4 + 2] * rsqrtf(var[c4 + 2] + BN_EPS);
        o.z = fmaxf((acc.z * dv + cb[c4 + 2] - mean[c4 + 2]) * s + beta[c4 + 2], 0.f);
        s = gamma[c4 + 3] * rsqrtf(var[c4 + 3] + BN_EPS);
        o.w = fmaxf((acc.w * dv + cb[c4 + 3] - mean[c4 + 3]) * s + beta[c4 + 3], 0.f);
    }

    if (!last) {
        ((float4*)(g_h + (size_t)n * 128))[lane] = o;
    } else {
        int b = batch[n];
        float* dp = g_pool + (size_t)b * 128 + lane * 4;
        asm volatile("red.global.add.v4.f32 [%0], {%1,%2,%3,%4};"
                     :: "l"(dp), "f"(o.x), "f"(o.y), "f"(o.z), "f"(o.w) : "memory");
        if (lane == 0) atomicAdd(&g_cnt[b], 1);
    }
}

// ---------------- MLP head: one block per graph ----------------
__global__ void mlp_kernel(const float* __restrict__ fc1w, const float* __restrict__ fc1b,
                           const float* __restrict__ fc2w, const float* __restrict__ fc2b,
                           float* __restrict__ out)
{
    __shared__ float gv[128];
    __shared__ float hid[64];
    int g = blockIdx.x;
    int t = threadIdx.x;           // 64 threads
    float cnt = fmaxf((float)g_cnt[g], 1.0f);
    float inv = 1.0f / cnt;
    gv[t]      = g_pool[g * 128 + t]      * inv;
    gv[t + 64] = g_pool[g * 128 + 64 + t] * inv;
    __syncthreads();
    float acc = fc1b[t];
#pragma unroll 8
    for (int k = 0; k < 128; k++) acc = fmaf(gv[k], fc1w[k * 64 + t], acc);
    hid[t] = fmaxf(acc, 0.f);
    __syncthreads();
    if (t < C_CLASSES) {
        float o = fc2b[t];
#pragma unroll
        for (int j = 0; j < 64; j++) o = fmaf(hid[j], fc2w[j * C_CLASSES + t], o);
        out[g * C_CLASSES + t] = o;
    }
}

__global__ void tail_kernel(float* __restrict__ out, int out_size) {
    int i = G_GRAPHS * C_CLASSES + blockIdx.x * blockDim.x + threadIdx.x;
    if (i < out_size) out[i] = 0.f;
}

// ---------------- launcher ----------------
extern "C" void kernel_launch(void* const* d_in, const int* in_sizes, int n_in,
                              void* d_out, int out_size)
{
    const float* x      = (const float*)d_in[0];
    const int*   ei     = (const int*)d_in[1];
    const int*   batch  = (const int*)d_in[2];
    const float* w_in   = (const float*)d_in[3];
    const float* b_in   = (const float*)d_in[4];
    const float* conv_w = (const float*)d_in[5];
    const float* conv_b = (const float*)d_in[6];
    const float* bn_g   = (const float*)d_in[7];
    const float* bn_b   = (const float*)d_in[8];
    const float* bn_m   = (const float*)d_in[9];
    const float* bn_v   = (const float*)d_in[10];
    const float* fc1w   = (const float*)d_in[11];
    const float* fc1b   = (const float*)d_in[12];
    const float* fc2w   = (const float*)d_in[13];
    const float* fc2b   = (const float*)d_in[14];
    float*       out    = (float*)d_out;

    const int SMEM = 128 * 128 * 4 + 64 * 128 * 8;   // 128 KB (W f32 + A dup f32x2)
    cudaFuncSetAttribute(gemm_kernel, cudaFuncAttributeMaxDynamicSharedMemorySize, SMEM);

    zero_kernel    <<<(N_NODES + 255) / 256, 256>>>();
    degree_kernel  <<<(E_EDGES + 255) / 256, 256>>>(ei);
    scan_kernel    <<<1, SCAN_T>>>();
    fill_csr_kernel<<<(E_EDGES + 255) / 256, 256>>>(ei);

    // input projection
    gemm_kernel<<<(N_NODES + 63) / 64, 256, SMEM>>>(x, w_in, b_in, 0);

    const unsigned node_warp_blocks = ((unsigned)N_NODES * 32u + 255) / 256;

    for (int l = 0; l < L_LAYERS; l++) {
        gemm_kernel<<<(N_NODES + 63) / 64, 256, SMEM>>>(nullptr, conv_w + (size_t)l * 128 * 128, nullptr, 1);
        agg_kernel <<<node_warp_blocks, 256>>>(conv_b + l * 128,
                                               bn_g + l * 128, bn_b + l * 128,
                                               bn_m + l * 128, bn_v + l * 128,
                                               batch, (l == L_LAYERS - 1) ? 1 : 0);
    }

    mlp_kernel<<<G_GRAPHS, 64>>>(fc1w, fc1b, fc2w, fc2b, out);

    int tail = out_size - G_GRAPHS * C_CLASSES;
    if (tail > 0) tail_kernel<<<(tail + 255) / 256, 256>>>(out, out_size);
}

// round 7
// speedup vs baseline: 1.2023x; 1.2023x over previous
#include <cuda_runtime.h>

#define N_NODES   100000
#define E_EDGES   1600000
#define H_DIM     128
#define L_LAYERS  4
#define C_CLASSES 12
#define G_GRAPHS  512
#define BN_EPS    1e-5f

#define SCAN_T    1024
#define CHUNK     ((N_NODES + SCAN_T - 1) / SCAN_T)   // 98

#define FMA2(d, a, b, c) asm("fma.rn.f32x2 %0, %1, %2, %3;" : "=l"(d) : "l"(a), "l"(b), "l"(c))
#define UNPACK2(lo, hi, p) asm("mov.b64 {%0, %1}, %2;" : "=f"(lo), "=f"(hi) : "l"(p))

// ---------------- device scratch (no allocation allowed) ----------------
__device__ __align__(128) float g_h  [N_NODES * H_DIM];   // activations
__device__ __align__(128) float g_hw [N_NODES * H_DIM];   // (h @ W) * dinv[row]
__device__ __align__(128) float g_dinv[N_NODES];
__device__ __align__(128) int   g_deg [N_NODES];
__device__ __align__(128) int   g_rowstart[N_NODES + 1];
__device__ __align__(128) int   g_cursor  [N_NODES];
__device__ __align__(128) int   g_csr_src [E_EDGES];
__device__ __align__(128) float g_pool[G_GRAPHS * H_DIM];
__device__ __align__(128) int   g_cnt [G_GRAPHS];

// ---------------- zero / degree / dinv ----------------
__global__ void zero_kernel() {
    int i = blockIdx.x * blockDim.x + threadIdx.x;
    if (i < N_NODES)          g_deg[i] = 0;
    if (i < G_GRAPHS * H_DIM) g_pool[i] = 0.f;
    if (i < G_GRAPHS)         g_cnt[i] = 0;
}

__global__ void degree_kernel(const int* __restrict__ ei) {
    int e = blockIdx.x * blockDim.x + threadIdx.x;
    if (e < E_EDGES) atomicAdd(&g_deg[ei[E_EDGES + e]], 1);
}

// single-block exclusive scan of g_deg -> g_rowstart / g_cursor, plus dinv
__global__ void __launch_bounds__(SCAN_T) scan_kernel() {
    __shared__ int part[SCAN_T];
    int t  = threadIdx.x;
    int lo = t * CHUNK;
    int hi = min(lo + CHUNK, N_NODES);
    int s = 0;
    for (int i = lo; i < hi; i++) s += g_deg[i];
    part[t] = s;
    __syncthreads();
    for (int d = 1; d < SCAN_T; d <<= 1) {
        int v = (t >= d) ? part[t - d] : 0;
        __syncthreads();
        part[t] += v;
        __syncthreads();
    }
    int run = part[t] - s;
    for (int i = lo; i < hi; i++) {
        g_rowstart[i] = run;
        g_cursor[i]   = run;
        int dg = g_deg[i];
        g_dinv[i] = rsqrtf((float)dg + 1.0f);
        run += dg;
    }
    if (t == SCAN_T - 1) g_rowstart[N_NODES] = run;
}

__global__ void fill_csr_kernel(const int* __restrict__ ei) {
    int e = blockIdx.x * blockDim.x + threadIdx.x;
    if (e < E_EDGES) {
        int s = ei[e];
        int d = ei[E_EDGES + e];
        int pos = atomicAdd(&g_cursor[d], 1);
        g_csr_src[pos] = s;
    }
}

// ---------------- GEMM (k-split FFMA2): [N,128] @ [128,128] ----------------
// acc f32x2: lo accumulates even-k terms, hi odd-k terms; final = lo + hi.
// W stored in smem k-pair interleaved: Ws2[k2*128 + c] = {W[2k2][c], W[2k2+1][c]}
// mode 0: g_h  = relu(x @ W + bias)          (A = x param)
// mode 1: g_hw = (g_h @ W) * dinv[row]
__global__ void __launch_bounds__(256, 2) gemm_kernel(
    const float* __restrict__ A_in, const float* __restrict__ W,
    const float* __restrict__ bias, int mode)
{
    extern __shared__ float sm[];
    unsigned long long* Ws2 = (unsigned long long*)sm;     // [64][128] pairs, 64 KB
    float* As = sm + 128 * 128;                            // [64][128] f32, 32 KB

    const float* A = (mode == 0) ? A_in : g_h;
    int tid  = threadIdx.x;
    int row0 = blockIdx.x * 64;

    // load + pair-interleave W: 2048 items, item = (k2, c4)
    const float4* W4 = (const float4*)W;
#pragma unroll
    for (int i = 0; i < 8; i++) {
        int idx = tid + 256 * i;
        int k2  = idx >> 5;
        int c4  = idx & 31;
        float4 w0 = W4[(2 * k2)     * 32 + c4];
        float4 w1 = W4[(2 * k2 + 1) * 32 + c4];
        float4* dst = (float4*)(Ws2 + k2 * 128 + c4 * 4);
        dst[0] = make_float4(w0.x, w1.x, w0.y, w1.y);
        dst[1] = make_float4(w0.z, w1.z, w0.w, w1.w);
    }

    // load A tile (64 rows x 128) plain f32
    float4* As4 = (float4*)As;
#pragma unroll
    for (int i = 0; i < 8; i++) {
        int idx = tid + 256 * i;
        int r   = idx >> 5;
        float4 v = make_float4(0.f, 0.f, 0.f, 0.f);
        if (row0 + r < N_NODES)
            v = ((const float4*)(A + (size_t)(row0 + r) * 128))[idx & 31];
        As4[idx] = v;
    }
    __syncthreads();

    int warp = tid >> 5, lane = tid & 31;
    unsigned long long acc2[8][4];
#pragma unroll
    for (int r = 0; r < 8; r++)
#pragma unroll
        for (int c = 0; c < 4; c++) acc2[r][c] = 0ull;

    const float* Arow = As + warp * 8 * 128;

    for (int k2b = 0; k2b < 32; k2b++) {
        // batch a-pairs for 2 k2 steps: LDS.128 broadcast per row
        ulonglong2 a4[8];
#pragma unroll
        for (int r = 0; r < 8; r++)
            a4[r] = *((const ulonglong2*)(Arow + r * 128 + 4 * k2b));
#pragma unroll
        for (int h = 0; h < 2; h++) {
            int k2 = 2 * k2b + h;
            const unsigned long long* wrow = Ws2 + k2 * 128 + 4 * lane;
            ulonglong2 wA = ((const ulonglong2*)wrow)[0];   // cols 4l, 4l+1
            ulonglong2 wB = ((const ulonglong2*)wrow)[1];   // cols 4l+2, 4l+3
#pragma unroll
            for (int r = 0; r < 8; r++) {
                unsigned long long a2 = h ? a4[r].y : a4[r].x;
                FMA2(acc2[r][0], a2, wA.x, acc2[r][0]);
                FMA2(acc2[r][1], a2, wA.y, acc2[r][1]);
                FMA2(acc2[r][2], a2, wB.x, acc2[r][2]);
                FMA2(acc2[r][3], a2, wB.y, acc2[r][3]);
            }
        }
    }

    if (mode == 0) {
        float4 bv = ((const float4*)bias)[lane];
#pragma unroll
        for (int r = 0; r < 8; r++) {
            int row = row0 + warp * 8 + r;
            if (row < N_NODES) {
                float lo, hi;
                float4 o;
                UNPACK2(lo, hi, acc2[r][0]); o.x = fmaxf(lo + hi + bv.x, 0.f);
                UNPACK2(lo, hi, acc2[r][1]); o.y = fmaxf(lo + hi + bv.y, 0.f);
                UNPACK2(lo, hi, acc2[r][2]); o.z = fmaxf(lo + hi + bv.z, 0.f);
                UNPACK2(lo, hi, acc2[r][3]); o.w = fmaxf(lo + hi + bv.w, 0.f);
                ((float4*)(g_h + (size_t)row * 128))[lane] = o;
            }
        }
    } else {
#pragma unroll
        for (int r = 0; r < 8; r++) {
            int row = row0 + warp * 8 + r;
            if (row < N_NODES) {
                float dv = g_dinv[row];
                float lo, hi;
                float4 o;
                UNPACK2(lo, hi, acc2[r][0]); o.x = (lo + hi) * dv;
                UNPACK2(lo, hi, acc2[r][1]); o.y = (lo + hi) * dv;
                UNPACK2(lo, hi, acc2[r][2]); o.z = (lo + hi) * dv;
                UNPACK2(lo, hi, acc2[r][3]); o.w = (lo + hi) * dv;
                ((float4*)(g_hw + (size_t)row * 128))[lane] = o;
            }
        }
    }
}

// ---------------- fused aggregation + BN + ReLU (warp per dst node) ----------------
// h[n] = relu( BN( ( g_hw[n] + sum_{src->n} g_hw[src] ) * dinv[n] + conv_b ) )
// last=1: additionally reduce into g_pool[batch[n]] and skip the g_h store.
__global__ void __launch_bounds__(256) agg_kernel(
    const float* __restrict__ cb,
    const float* __restrict__ gamma,
    const float* __restrict__ beta,
    const float* __restrict__ mean,
    const float* __restrict__ var,
    const int* __restrict__ batch, int last)
{
    unsigned gtid = blockIdx.x * blockDim.x + threadIdx.x;
    unsigned n    = gtid >> 5;
    int lane      = threadIdx.x & 31;
    if (n >= N_NODES) return;

    float4 acc = ((const float4*)(g_hw + (size_t)n * 128))[lane];   // self term

    int start = g_rowstart[n];
    int end   = g_rowstart[n + 1];
    for (int base = start; base < end; base += 32) {
        int cnt = min(32, end - base);
        int src = (base + lane < end) ? g_csr_src[base + lane] : 0;
#pragma unroll 4
        for (int j = 0; j < cnt; j++) {
            int s = __shfl_sync(0xffffffffu, src, j);
            float4 v = __ldg((const float4*)(g_hw + (size_t)s * 128) + lane);
            acc.x += v.x; acc.y += v.y; acc.z += v.z; acc.w += v.w;
        }
    }

    float dv = g_dinv[n];
    int c4   = lane * 4;
    float4 o;
    {
        float s = gamma[c4 + 0] * rsqrtf(var[c4 + 0] + BN_EPS);
        o.x = fmaxf((acc.x * dv + cb[c4 + 0] - mean[c4 + 0]) * s + beta[c4 + 0], 0.f);
        s = gamma[c4 + 1] * rsqrtf(var[c4 + 1] + BN_EPS);
        o.y = fmaxf((acc.y * dv + cb[c4 + 1] - mean[c4 + 1]) * s + beta[c4 + 1], 0.f);
        s = gamma[c4 + 2] * rsqrtf(var[c4 + 2] + BN_EPS);
        o.z = fmaxf((acc.z * dv + cb[c4 + 2] - mean[c4 + 2]) * s + beta[c4 + 2], 0.f);
        s = gamma[c4 + 3] * rsqrtf(var[c4 + 3] + BN_EPS);
        o.w = fmaxf((acc.w * dv + cb[c4 + 3] - mean[c4 + 3]) * s + beta[c4 + 3], 0.f);
    }

    if (!last) {
        ((float4*)(g_h + (size_t)n * 128))[lane] = o;
    } else {
        int b = batch[n];
        float* dp = g_pool + (size_t)b * 128 + lane * 4;
        asm volatile("red.global.add.v4.f32 [%0], {%1,%2,%3,%4};"
                     :: "l"(dp), "f"(o.x), "f"(o.y), "f"(o.z), "f"(o.w) : "memory");
        if (lane == 0) atomicAdd(&g_cnt[b], 1);
    }
}

// ---------------- MLP head: one block per graph ----------------
__global__ void mlp_kernel(const float* __restrict__ fc1w, const float* __restrict__ fc1b,
                           const float* __restrict__ fc2w, const float* __restrict__ fc2b,
                           float* __restrict__ out)
{
    __shared__ float gv[128];
    __shared__ float hid[64];
    int g = blockIdx.x;
    int t = threadIdx.x;           // 64 threads
    float cnt = fmaxf((float)g_cnt[g], 1.0f);
    float inv = 1.0f / cnt;
    gv[t]      = g_pool[g * 128 + t]      * inv;
    gv[t + 64] = g_pool[g * 128 + 64 + t] * inv;
    __syncthreads();
    float acc = fc1b[t];
#pragma unroll 8
    for (int k = 0; k < 128; k++) acc = fmaf(gv[k], fc1w[k * 64 + t], acc);
    hid[t] = fmaxf(acc, 0.f);
    __syncthreads();
    if (t < C_CLASSES) {
        float o = fc2b[t];
#pragma unroll
        for (int j = 0; j < 64; j++) o = fmaf(hid[j], fc2w[j * C_CLASSES + t], o);
        out[g * C_CLASSES + t] = o;
    }
}

__global__ void tail_kernel(float* __restrict__ out, int out_size) {
    int i = G_GRAPHS * C_CLASSES + blockIdx.x * blockDim.x + threadIdx.x;
    if (i < out_size) out[i] = 0.f;
}

// ---------------- launcher ----------------
extern "C" void kernel_launch(void* const* d_in, const int* in_sizes, int n_in,
                              void* d_out, int out_size)
{
    const float* x      = (const float*)d_in[0];
    const int*   ei     = (const int*)d_in[1];
    const int*   batch  = (const int*)d_in[2];
    const float* w_in   = (const float*)d_in[3];
    const float* b_in   = (const float*)d_in[4];
    const float* conv_w = (const float*)d_in[5];
    const float* conv_b = (const float*)d_in[6];
    const float* bn_g   = (const float*)d_in[7];
    const float* bn_b   = (const float*)d_in[8];
    const float* bn_m   = (const float*)d_in[9];
    const float* bn_v   = (const float*)d_in[10];
    const float* fc1w   = (const float*)d_in[11];
    const float* fc1b   = (const float*)d_in[12];
    const float* fc2w   = (const float*)d_in[13];
    const float* fc2b   = (const float*)d_in[14];
    float*       out    = (float*)d_out;

    const int SMEM = 128 * 128 * 4 + 64 * 128 * 4;   // 96 KB (W pairs + A f32)
    cudaFuncSetAttribute(gemm_kernel, cudaFuncAttributeMaxDynamicSharedMemorySize, SMEM);

    zero_kernel    <<<(N_NODES + 255) / 256, 256>>>();
    degree_kernel  <<<(E_EDGES + 255) / 256, 256>>>(ei);
    scan_kernel    <<<1, SCAN_T>>>();
    fill_csr_kernel<<<(E_EDGES + 255) / 256, 256>>>(ei);

    // input projection
    gemm_kernel<<<(N_NODES + 63) / 64, 256, SMEM>>>(x, w_in, b_in, 0);

    const unsigned node_warp_blocks = ((unsigned)N_NODES * 32u + 255) / 256;

    for (int l = 0; l < L_LAYERS; l++) {
        gemm_kernel<<<(N_NODES + 63) / 64, 256, SMEM>>>(nullptr, conv_w + (size_t)l * 128 * 128, nullptr, 1);
        agg_kernel <<<node_warp_blocks, 256>>>(conv_b + l * 128,
                                               bn_g + l * 128, bn_b + l * 128,
                                               bn_m + l * 128, bn_v + l * 128,
                                               batch, (l == L_LAYERS - 1) ? 1 : 0);
    }

    mlp_kernel<<<G_GRAPHS, 64>>>(fc1w, fc1b, fc2w, fc2b, out);

    int tail = out_size - G_GRAPHS * C_CLASSES;
    if (tail > 0) tail_kernel<<<(tail + 255) / 256, 256>>>(out, out_size);
}

// round 8
// speedup vs baseline: 1.2709x; 1.0570x over previous
#include <cuda_runtime.h>
#include <cuda_fp16.h>

#define N_NODES   100000
#define E_EDGES   1600000
#define H_DIM     128
#define L_LAYERS  4
#define C_CLASSES 12
#define G_GRAPHS  512
#define BN_EPS    1e-5f

#define SCAN_T    1024
#define CHUNK     ((N_NODES + SCAN_T - 1) / SCAN_T)   // 98

#define FMA2(d, a, b, c) asm("fma.rn.f32x2 %0, %1, %2, %3;" : "=l"(d) : "l"(a), "l"(b), "l"(c))
#define UNPACK2(lo, hi, p) asm("mov.b64 {%0, %1}, %2;" : "=f"(lo), "=f"(hi) : "l"(p))

// ---------------- device scratch (no allocation allowed) ----------------
__device__ __align__(128) float  g_h  [N_NODES * H_DIM];   // activations (fp32)
__device__ __align__(128) __half g_hwh[N_NODES * H_DIM];   // (h @ W) * dinv[row], fp16
__device__ __align__(128) float  g_dinv[N_NODES];
__device__ __align__(128) int    g_deg [N_NODES];
__device__ __align__(128) int    g_rowstart[N_NODES + 1];
__device__ __align__(128) int    g_cursor  [N_NODES];
__device__ __align__(128) int    g_csr_src [E_EDGES];
__device__ __align__(128) float  g_pool[G_GRAPHS * H_DIM];
__device__ __align__(128) int    g_cnt [G_GRAPHS];

// ---------------- zero / degree / dinv ----------------
__global__ void zero_kernel() {
    int i = blockIdx.x * blockDim.x + threadIdx.x;
    if (i < N_NODES)          g_deg[i] = 0;
    if (i < G_GRAPHS * H_DIM) g_pool[i] = 0.f;
    if (i < G_GRAPHS)         g_cnt[i] = 0;
}

__global__ void degree_kernel(const int* __restrict__ ei) {
    int e = blockIdx.x * blockDim.x + threadIdx.x;
    if (e < E_EDGES) atomicAdd(&g_deg[ei[E_EDGES + e]], 1);
}

// single-block exclusive scan of g_deg -> g_rowstart / g_cursor, plus dinv
__global__ void __launch_bounds__(SCAN_T) scan_kernel() {
    __shared__ int part[SCAN_T];
    int t  = threadIdx.x;
    int lo = t * CHUNK;
    int hi = min(lo + CHUNK, N_NODES);
    int s = 0;
    for (int i = lo; i < hi; i++) s += g_deg[i];
    part[t] = s;
    __syncthreads();
    for (int d = 1; d < SCAN_T; d <<= 1) {
        int v = (t >= d) ? part[t - d] : 0;
        __syncthreads();
        part[t] += v;
        __syncthreads();
    }
    int run = part[t] - s;
    for (int i = lo; i < hi; i++) {
        g_rowstart[i] = run;
        g_cursor[i]   = run;
        int dg = g_deg[i];
        g_dinv[i] = rsqrtf((float)dg + 1.0f);
        run += dg;
    }
    if (t == SCAN_T - 1) g_rowstart[N_NODES] = run;
}

__global__ void fill_csr_kernel(const int* __restrict__ ei) {
    int e = blockIdx.x * blockDim.x + threadIdx.x;
    if (e < E_EDGES) {
        int s = ei[e];
        int d = ei[E_EDGES + e];
        int pos = atomicAdd(&g_cursor[d], 1);
        g_csr_src[pos] = s;
    }
}

// ---------------- GEMM (k-split FFMA2): [N,128] @ [128,128] ----------------
// mode 0: g_h   = relu(x @ W + bias)  (fp32, A = x param)
// mode 1: g_hwh = half((g_h @ W) * dinv[row])
__global__ void __launch_bounds__(256, 2) gemm_kernel(
    const float* __restrict__ A_in, const float* __restrict__ W,
    const float* __restrict__ bias, int mode)
{
    extern __shared__ float sm[];
    unsigned long long* Ws2 = (unsigned long long*)sm;     // [64][128] k-pairs, 64 KB
    float* As = sm + 128 * 128;                            // [64][128] f32, 32 KB

    const float* A = (mode == 0) ? A_in : g_h;
    int tid  = threadIdx.x;
    int row0 = blockIdx.x * 64;

    const float4* W4 = (const float4*)W;
#pragma unroll
    for (int i = 0; i < 8; i++) {
        int idx = tid + 256 * i;
        int k2  = idx >> 5;
        int c4  = idx & 31;
        float4 w0 = W4[(2 * k2)     * 32 + c4];
        float4 w1 = W4[(2 * k2 + 1) * 32 + c4];
        float4* dst = (float4*)(Ws2 + k2 * 128 + c4 * 4);
        dst[0] = make_float4(w0.x, w1.x, w0.y, w1.y);
        dst[1] = make_float4(w0.z, w1.z, w0.w, w1.w);
    }

    float4* As4 = (float4*)As;
#pragma unroll
    for (int i = 0; i < 8; i++) {
        int idx = tid + 256 * i;
        int r   = idx >> 5;
        float4 v = make_float4(0.f, 0.f, 0.f, 0.f);
        if (row0 + r < N_NODES)
            v = ((const float4*)(A + (size_t)(row0 + r) * 128))[idx & 31];
        As4[idx] = v;
    }
    __syncthreads();

    int warp = tid >> 5, lane = tid & 31;
    unsigned long long acc2[8][4];
#pragma unroll
    for (int r = 0; r < 8; r++)
#pragma unroll
        for (int c = 0; c < 4; c++) acc2[r][c] = 0ull;

    const float* Arow = As + warp * 8 * 128;

    for (int k2b = 0; k2b < 32; k2b++) {
        ulonglong2 a4[8];
#pragma unroll
        for (int r = 0; r < 8; r++)
            a4[r] = *((const ulonglong2*)(Arow + r * 128 + 4 * k2b));
#pragma unroll
        for (int h = 0; h < 2; h++) {
            int k2 = 2 * k2b + h;
            const unsigned long long* wrow = Ws2 + k2 * 128 + 4 * lane;
            ulonglong2 wA = ((const ulonglong2*)wrow)[0];
            ulonglong2 wB = ((const ulonglong2*)wrow)[1];
#pragma unroll
            for (int r = 0; r < 8; r++) {
                unsigned long long a2 = h ? a4[r].y : a4[r].x;
                FMA2(acc2[r][0], a2, wA.x, acc2[r][0]);
                FMA2(acc2[r][1], a2, wA.y, acc2[r][1]);
                FMA2(acc2[r][2], a2, wB.x, acc2[r][2]);
                FMA2(acc2[r][3], a2, wB.y, acc2[r][3]);
            }
        }
    }

    if (mode == 0) {
        float4 bv = ((const float4*)bias)[lane];
#pragma unroll
        for (int r = 0; r < 8; r++) {
            int row = row0 + warp * 8 + r;
            if (row < N_NODES) {
                float lo, hi;
                float4 o;
                UNPACK2(lo, hi, acc2[r][0]); o.x = fmaxf(lo + hi + bv.x, 0.f);
                UNPACK2(lo, hi, acc2[r][1]); o.y = fmaxf(lo + hi + bv.y, 0.f);
                UNPACK2(lo, hi, acc2[r][2]); o.z = fmaxf(lo + hi + bv.z, 0.f);
                UNPACK2(lo, hi, acc2[r][3]); o.w = fmaxf(lo + hi + bv.w, 0.f);
                ((float4*)(g_h + (size_t)row * 128))[lane] = o;
            }
        }
    } else {
#pragma unroll
        for (int r = 0; r < 8; r++) {
            int row = row0 + warp * 8 + r;
            if (row < N_NODES) {
                float dv = g_dinv[row];
                float lo, hi;
                float4 o;
                UNPACK2(lo, hi, acc2[r][0]); o.x = (lo + hi) * dv;
                UNPACK2(lo, hi, acc2[r][1]); o.y = (lo + hi) * dv;
                UNPACK2(lo, hi, acc2[r][2]); o.z = (lo + hi) * dv;
                UNPACK2(lo, hi, acc2[r][3]); o.w = (lo + hi) * dv;
                __half2 h0 = __floats2half2_rn(o.x, o.y);
                __half2 h1 = __floats2half2_rn(o.z, o.w);
                uint2 st;
                st.x = *(unsigned int*)&h0;
                st.y = *(unsigned int*)&h1;
                ((uint2*)(g_hwh + (size_t)row * 128))[lane] = st;
            }
        }
    }
}

// ---------------- fused aggregation + BN + ReLU (warp per dst node) ----------------
// h[n] = relu( BN( ( hw[n] + sum_{src->n} hw[src] ) * dinv[n] + conv_b ) )
// last=1: reduce into g_pool[batch[n]] instead of storing g_h.
__global__ void __launch_bounds__(256) agg_kernel(
    const float* __restrict__ cb,
    const float* __restrict__ gamma,
    const float* __restrict__ beta,
    const float* __restrict__ mean,
    const float* __restrict__ var,
    const int* __restrict__ batch, int last)
{
    unsigned gtid = blockIdx.x * blockDim.x + threadIdx.x;
    unsigned n    = gtid >> 5;
    int lane      = threadIdx.x & 31;
    if (n >= N_NODES) return;

    // self term (dims 4*lane .. 4*lane+3)
    float4 acc;
    {
        uint2 raw = ((const uint2*)(g_hwh + (size_t)n * 128))[lane];
        __half2 p0 = *(__half2*)&raw.x;
        __half2 p1 = *(__half2*)&raw.y;
        float2 f0 = __half22float2(p0);
        float2 f1 = __half22float2(p1);
        acc = make_float4(f0.x, f0.y, f1.x, f1.y);
    }

    int start = g_rowstart[n];
    int end   = g_rowstart[n + 1];
    for (int base = start; base < end; base += 32) {
        int cnt = min(32, end - base);
        int src = (base + lane < end) ? g_csr_src[base + lane] : 0;
#pragma unroll 4
        for (int j = 0; j < cnt; j++) {
            int s = __shfl_sync(0xffffffffu, src, j);
            uint2 raw = __ldg((const uint2*)(g_hwh + (size_t)s * 128) + lane);
            __half2 p0 = *(__half2*)&raw.x;
            __half2 p1 = *(__half2*)&raw.y;
            float2 f0 = __half22float2(p0);
            float2 f1 = __half22float2(p1);
            acc.x += f0.x; acc.y += f0.y; acc.z += f1.x; acc.w += f1.y;
        }
    }

    float dv = g_dinv[n];
    int c4   = lane * 4;
    float4 o;
    {
        float s = gamma[c4 + 0] * rsqrtf(var[c4 + 0] + BN_EPS);
        o.x = fmaxf((acc.x * dv + cb[c4 + 0] - mean[c4 + 0]) * s + beta[c4 + 0], 0.f);
        s = gamma[c4 + 1] * rsqrtf(var[c4 + 1] + BN_EPS);
        o.y = fmaxf((acc.y * dv + cb[c4 + 1] - mean[c4 + 1]) * s + beta[c4 + 1], 0.f);
        s = gamma[c4 + 2] * rsqrtf(var[c4 + 2] + BN_EPS);
        o.z = fmaxf((acc.z * dv + cb[c4 + 2] - mean[c4 + 2]) * s + beta[c4 + 2], 0.f);
        s = gamma[c4 + 3] * rsqrtf(var[c4 + 3] + BN_EPS);
        o.w = fmaxf((acc.w * dv + cb[c4 + 3] - mean[c4 + 3]) * s + beta[c4 + 3], 0.f);
    }

    if (!last) {
        ((float4*)(g_h + (size_t)n * 128))[lane] = o;
    } else {
        int b = batch[n];
        float* dp = g_pool + (size_t)b * 128 + lane * 4;
        asm volatile("red.global.add.v4.f32 [%0], {%1,%2,%3,%4};"
                     :: "l"(dp), "f"(o.x), "f"(o.y), "f"(o.z), "f"(o.w) : "memory");
        if (lane == 0) atomicAdd(&g_cnt[b], 1);
    }
}

// ---------------- MLP head: one block per graph ----------------
__global__ void mlp_kernel(const float* __restrict__ fc1w, const float* __restrict__ fc1b,
                           const float* __restrict__ fc2w, const float* __restrict__ fc2b,
                           float* __restrict__ out)
{
    __shared__ float gv[128];
    __shared__ float hid[64];
    int g = blockIdx.x;
    int t = threadIdx.x;           // 64 threads
    float cnt = fmaxf((float)g_cnt[g], 1.0f);
    float inv = 1.0f / cnt;
    gv[t]      = g_pool[g * 128 + t]      * inv;
    gv[t + 64] = g_pool[g * 128 + 64 + t] * inv;
    __syncthreads();
    float acc = fc1b[t];
#pragma unroll 8
    for (int k = 0; k < 128; k++) acc = fmaf(gv[k], fc1w[k * 64 + t], acc);
    hid[t] = fmaxf(acc, 0.f);
    __syncthreads();
    if (t < C_CLASSES) {
        float o = fc2b[t];
#pragma unroll
        for (int j = 0; j < 64; j++) o = fmaf(hid[j], fc2w[j * C_CLASSES + t], o);
        out[g * C_CLASSES + t] = o;
    }
}

__global__ void tail_kernel(float* __restrict__ out, int out_size) {
    int i = G_GRAPHS * C_CLASSES + blockIdx.x * blockDim.x + threadIdx.x;
    if (i < out_size) out[i] = 0.f;
}

// ---------------- launcher ----------------
extern "C" void kernel_launch(void* const* d_in, const int* in_sizes, int n_in,
                              void* d_out, int out_size)
{
    const float* x      = (const float*)d_in[0];
    const int*   ei     = (const int*)d_in[1];
    const int*   batch  = (const int*)d_in[2];
    const float* w_in   = (const float*)d_in[3];
    const float* b_in   = (const float*)d_in[4];
    const float* conv_w = (const float*)d_in[5];
    const float* conv_b = (const float*)d_in[6];
    const float* bn_g   = (const float*)d_in[7];
    const float* bn_b   = (const float*)d_in[8];
    const float* bn_m   = (const float*)d_in[9];
    const float* bn_v   = (const float*)d_in[10];
    const float* fc1w   = (const float*)d_in[11];
    const float* fc1b   = (const float*)d_in[12];
    const float* fc2w   = (const float*)d_in[13];
    const float* fc2b   = (const float*)d_in[14];
    float*       out    = (float*)d_out;

    const int SMEM = 128 * 128 * 4 + 64 * 128 * 4;   // 96 KB
    cudaFuncSetAttribute(gemm_kernel, cudaFuncAttributeMaxDynamicSharedMemorySize, SMEM);

    zero_kernel    <<<(N_NODES + 255) / 256, 256>>>();
    degree_kernel  <<<(E_EDGES + 255) / 256, 256>>>(ei);
    scan_kernel    <<<1, SCAN_T>>>();
    fill_csr_kernel<<<(E_EDGES + 255) / 256, 256>>>(ei);

    // input projection
    gemm_kernel<<<(N_NODES + 63) / 64, 256, SMEM>>>(x, w_in, b_in, 0);

    const unsigned node_warp_blocks = ((unsigned)N_NODES * 32u + 255) / 256;

    for (int l = 0; l < L_LAYERS; l++) {
        gemm_kernel<<<(N_NODES + 63) / 64, 256, SMEM>>>(nullptr, conv_w + (size_t)l * 128 * 128, nullptr, 1);
        agg_kernel <<<node_warp_blocks, 256>>>(conv_b + l * 128,
                                               bn_g + l * 128, bn_b + l * 128,
                                               bn_m + l * 128, bn_v + l * 128,
                                               batch, (l == L_LAYERS - 1) ? 1 : 0);
    }

    mlp_kernel<<<G_GRAPHS, 64>>>(fc1w, fc1b, fc2w, fc2b, out);

    int tail = out_size - G_GRAPHS * C_CLASSES;
    if (tail > 0) tail_kernel<<<(tail + 255) / 256, 256>>>(out, out_size);
}

// round 9
// speedup vs baseline: 1.7279x; 1.3596x over previous
#include <cuda_runtime.h>
#include <cuda_fp16.h>

#define N_NODES   100000
#define E_EDGES   1600000
#define H_DIM     128
#define L_LAYERS  4
#define C_CLASSES 12
#define G_GRAPHS  512
#define BN_EPS    1e-5f

#define SCAN_T    1024
#define CHUNK     ((N_NODES + SCAN_T - 1) / SCAN_T)   // 98

// smem strides (in uint32 units) chosen for conflict-free fragment loads
#define W_STRIDE  136
#define A_STRIDE  132

#define CVT_TF32(o, x) asm("cvt.rna.tf32.f32 %0, %1;" : "=r"(o) : "f"(x))
#define MMA_TF32(d, a0, a1, a2, a3, b0, b1) \
    asm("mma.sync.aligned.m16n8k8.row.col.f32.tf32.tf32.f32 " \
        "{%0,%1,%2,%3},{%4,%5,%6,%7},{%8,%9},{%0,%1,%2,%3};" \
        : "+f"((d)[0]), "+f"((d)[1]), "+f"((d)[2]), "+f"((d)[3]) \
        : "r"(a0), "r"(a1), "r"(a2), "r"(a3), "r"(b0), "r"(b1))

// ---------------- device scratch (no allocation allowed) ----------------
__device__ __align__(128) float  g_h  [N_NODES * H_DIM];   // activations (fp32)
__device__ __align__(128) __half g_hwh[N_NODES * H_DIM];   // (h @ W) * dinv[row], fp16
__device__ __align__(128) float  g_dinv[N_NODES];
__device__ __align__(128) int    g_deg [N_NODES];
__device__ __align__(128) int    g_rowstart[N_NODES + 1];
__device__ __align__(128) int    g_cursor  [N_NODES];
__device__ __align__(128) int    g_csr_src [E_EDGES];
__device__ __align__(128) float  g_pool[G_GRAPHS * H_DIM];
__device__ __align__(128) int    g_cnt [G_GRAPHS];

// ---------------- zero / degree / dinv ----------------
__global__ void zero_kernel() {
    int i = blockIdx.x * blockDim.x + threadIdx.x;
    if (i < N_NODES)          g_deg[i] = 0;
    if (i < G_GRAPHS * H_DIM) g_pool[i] = 0.f;
    if (i < G_GRAPHS)         g_cnt[i] = 0;
}

__global__ void degree_kernel(const int* __restrict__ ei) {
    int e = blockIdx.x * blockDim.x + threadIdx.x;
    if (e < E_EDGES) atomicAdd(&g_deg[ei[E_EDGES + e]], 1);
}

__global__ void __launch_bounds__(SCAN_T) scan_kernel() {
    __shared__ int part[SCAN_T];
    int t  = threadIdx.x;
    int lo = t * CHUNK;
    int hi = min(lo + CHUNK, N_NODES);
    int s = 0;
    for (int i = lo; i < hi; i++) s += g_deg[i];
    part[t] = s;
    __syncthreads();
    for (int d = 1; d < SCAN_T; d <<= 1) {
        int v = (t >= d) ? part[t - d] : 0;
        __syncthreads();
        part[t] += v;
        __syncthreads();
    }
    int run = part[t] - s;
    for (int i = lo; i < hi; i++) {
        g_rowstart[i] = run;
        g_cursor[i]   = run;
        int dg = g_deg[i];
        g_dinv[i] = rsqrtf((float)dg + 1.0f);
        run += dg;
    }
    if (t == SCAN_T - 1) g_rowstart[N_NODES] = run;
}

__global__ void fill_csr_kernel(const int* __restrict__ ei) {
    int e = blockIdx.x * blockDim.x + threadIdx.x;
    if (e < E_EDGES) {
        int s = ei[e];
        int d = ei[E_EDGES + e];
        int pos = atomicAdd(&g_cursor[d], 1);
        g_csr_src[pos] = s;
    }
}

// ---------------- GEMM (tf32 mma.sync): [N,128] @ [128,128] ----------------
// CTA: 64 rows x 128 cols, 8 warps = 4(m) x 2(n), warp tile 16x64.
// mode 0: g_h   = relu(x @ W + bias)            (A = x param, fp32 out)
// mode 1: g_hwh = half((g_h @ W) * dinv[row])   (fp16 out)
__global__ void __launch_bounds__(256, 2) gemm_kernel(
    const float* __restrict__ A_in, const float* __restrict__ W,
    const float* __restrict__ bias, int mode)
{
    extern __shared__ unsigned int smu[];
    unsigned int* Ws = smu;                     // [128][W_STRIDE]
    unsigned int* As = smu + 128 * W_STRIDE;    // [64][A_STRIDE]

    const float* A = (mode == 0) ? A_in : g_h;
    int tid  = threadIdx.x;
    int row0 = blockIdx.x * 64;

    // load W (tf32-rounded): 4096 float4 items
    const float4* W4 = (const float4*)W;
#pragma unroll
    for (int i = 0; i < 16; i++) {
        int idx = tid + 256 * i;            // float4 index
        int k   = idx >> 5;
        int c4  = idx & 31;
        float4 w = W4[idx];
        unsigned int* dst = Ws + k * W_STRIDE + c4 * 4;
        unsigned int t0, t1, t2, t3;
        CVT_TF32(t0, w.x); CVT_TF32(t1, w.y); CVT_TF32(t2, w.z); CVT_TF32(t3, w.w);
        dst[0] = t0; dst[1] = t1; dst[2] = t2; dst[3] = t3;
    }

    // load A tile (64 x 128, tf32-rounded, zero-pad OOB rows)
#pragma unroll
    for (int i = 0; i < 8; i++) {
        int idx = tid + 256 * i;
        int r   = idx >> 5;
        int c4  = idx & 31;
        float4 v = make_float4(0.f, 0.f, 0.f, 0.f);
        if (row0 + r < N_NODES)
            v = ((const float4*)(A + (size_t)(row0 + r) * 128))[c4];
        unsigned int* dst = As + r * A_STRIDE + c4 * 4;
        unsigned int t0, t1, t2, t3;
        CVT_TF32(t0, v.x); CVT_TF32(t1, v.y); CVT_TF32(t2, v.z); CVT_TF32(t3, v.w);
        dst[0] = t0; dst[1] = t1; dst[2] = t2; dst[3] = t3;
    }
    __syncthreads();

    int warp = tid >> 5, lane = tid & 31;
    int wm = warp >> 1;           // 0..3  (m groups of 16 rows)
    int wn = warp & 1;            // 0..1  (n halves of 64 cols)
    int g  = lane >> 2;           // 0..7
    int t  = lane & 3;            // 0..3

    float acc[8][4];
#pragma unroll
    for (int nt = 0; nt < 8; nt++)
#pragma unroll
        for (int c = 0; c < 4; c++) acc[nt][c] = 0.f;

    const unsigned int* a_base = As + (wm * 16 + g) * A_STRIDE;
    const unsigned int* b_base = Ws + wn * 64 + g;

#pragma unroll 4
    for (int ks = 0; ks < 16; ks++) {
        int kc = ks * 8;
        unsigned int a0 = a_base[kc + t];
        unsigned int a1 = a_base[8 * A_STRIDE + kc + t];
        unsigned int a2 = a_base[kc + t + 4];
        unsigned int a3 = a_base[8 * A_STRIDE + kc + t + 4];
        const unsigned int* b0p = b_base + (kc + t) * W_STRIDE;
        const unsigned int* b1p = b_base + (kc + t + 4) * W_STRIDE;
#pragma unroll
        for (int nt = 0; nt < 8; nt++) {
            unsigned int b0 = b0p[nt * 8];
            unsigned int b1 = b1p[nt * 8];
            MMA_TF32(acc[nt], a0, a1, a2, a3, b0, b1);
        }
    }

    // epilogue: rows r0 = row0 + wm*16 + g, r1 = r0 + 8; cols = wn*64 + nt*8 + 2t
    int r0 = row0 + wm * 16 + g;
    int r1 = r0 + 8;
    if (mode == 0) {
#pragma unroll
        for (int nt = 0; nt < 8; nt++) {
            int col = wn * 64 + nt * 8 + 2 * t;
            float b0 = bias[col], b1 = bias[col + 1];
            if (r0 < N_NODES) {
                float2 o = make_float2(fmaxf(acc[nt][0] + b0, 0.f),
                                       fmaxf(acc[nt][1] + b1, 0.f));
                *(float2*)(g_h + (size_t)r0 * 128 + col) = o;
            }
            if (r1 < N_NODES) {
                float2 o = make_float2(fmaxf(acc[nt][2] + b0, 0.f),
                                       fmaxf(acc[nt][3] + b1, 0.f));
                *(float2*)(g_h + (size_t)r1 * 128 + col) = o;
            }
        }
    } else {
        float dv0 = (r0 < N_NODES) ? g_dinv[r0] : 0.f;
        float dv1 = (r1 < N_NODES) ? g_dinv[r1] : 0.f;
#pragma unroll
        for (int nt = 0; nt < 8; nt++) {
            int col = wn * 64 + nt * 8 + 2 * t;
            if (r0 < N_NODES) {
                __half2 h = __floats2half2_rn(acc[nt][0] * dv0, acc[nt][1] * dv0);
                *(__half2*)(g_hwh + (size_t)r0 * 128 + col) = h;
            }
            if (r1 < N_NODES) {
                __half2 h = __floats2half2_rn(acc[nt][2] * dv1, acc[nt][3] * dv1);
                *(__half2*)(g_hwh + (size_t)r1 * 128 + col) = h;
            }
        }
    }
}

// ---------------- fused aggregation + BN + ReLU (warp per dst node) ----------------
__global__ void __launch_bounds__(256) agg_kernel(
    const float* __restrict__ cb,
    const float* __restrict__ gamma,
    const float* __restrict__ beta,
    const float* __restrict__ mean,
    const float* __restrict__ var,
    const int* __restrict__ batch, int last)
{
    unsigned gtid = blockIdx.x * blockDim.x + threadIdx.x;
    unsigned n    = gtid >> 5;
    int lane      = threadIdx.x & 31;
    if (n >= N_NODES) return;

    float4 acc;
    {
        uint2 raw = ((const uint2*)(g_hwh + (size_t)n * 128))[lane];
        float2 f0 = __half22float2(*(__half2*)&raw.x);
        float2 f1 = __half22float2(*(__half2*)&raw.y);
        acc = make_float4(f0.x, f0.y, f1.x, f1.y);
    }

    int start = g_rowstart[n];
    int end   = g_rowstart[n + 1];
    for (int base = start; base < end; base += 32) {
        int cnt = min(32, end - base);
        int src = (base + lane < end) ? g_csr_src[base + lane] : 0;
#pragma unroll 4
        for (int j = 0; j < cnt; j++) {
            int s = __shfl_sync(0xffffffffu, src, j);
            uint2 raw = __ldg((const uint2*)(g_hwh + (size_t)s * 128) + lane);
            float2 f0 = __half22float2(*(__half2*)&raw.x);
            float2 f1 = __half22float2(*(__half2*)&raw.y);
            acc.x += f0.x; acc.y += f0.y; acc.z += f1.x; acc.w += f1.y;
        }
    }

    float dv = g_dinv[n];
    int c4   = lane * 4;
    float4 o;
    {
        float s = gamma[c4 + 0] * rsqrtf(var[c4 + 0] + BN_EPS);
        o.x = fmaxf((acc.x * dv + cb[c4 + 0] - mean[c4 + 0]) * s + beta[c4 + 0], 0.f);
        s = gamma[c4 + 1] * rsqrtf(var[c4 + 1] + BN_EPS);
        o.y = fmaxf((acc.y * dv + cb[c4 + 1] - mean[c4 + 1]) * s + beta[c4 + 1], 0.f);
        s = gamma[c4 + 2] * rsqrtf(var[c4 + 2] + BN_EPS);
        o.z = fmaxf((acc.z * dv + cb[c4 + 2] - mean[c4 + 2]) * s + beta[c4 + 2], 0.f);
        s = gamma[c4 + 3] * rsqrtf(var[c4 + 3] + BN_EPS);
        o.w = fmaxf((acc.w * dv + cb[c4 + 3] - mean[c4 + 3]) * s + beta[c4 + 3], 0.f);
    }

    if (!last) {
        ((float4*)(g_h + (size_t)n * 128))[lane] = o;
    } else {
        int b = batch[n];
        float* dp = g_pool + (size_t)b * 128 + lane * 4;
        asm volatile("red.global.add.v4.f32 [%0], {%1,%2,%3,%4};"
                     :: "l"(dp), "f"(o.x), "f"(o.y), "f"(o.z), "f"(o.w) : "memory");
        if (lane == 0) atomicAdd(&g_cnt[b], 1);
    }
}

// ---------------- MLP head: one block per graph ----------------
__global__ void mlp_kernel(const float* __restrict__ fc1w, const float* __restrict__ fc1b,
                           const float* __restrict__ fc2w, const float* __restrict__ fc2b,
                           float* __restrict__ out)
{
    __shared__ float gv[128];
    __shared__ float hid[64];
    int g = blockIdx.x;
    int t = threadIdx.x;           // 64 threads
    float cnt = fmaxf((float)g_cnt[g], 1.0f);
    float inv = 1.0f / cnt;
    gv[t]      = g_pool[g * 128 + t]      * inv;
    gv[t + 64] = g_pool[g * 128 + 64 + t] * inv;
    __syncthreads();
    float acc = fc1b[t];
#pragma unroll 8
    for (int k = 0; k < 128; k++) acc = fmaf(gv[k], fc1w[k * 64 + t], acc);
    hid[t] = fmaxf(acc, 0.f);
    __syncthreads();
    if (t < C_CLASSES) {
        float o = fc2b[t];
#pragma unroll
        for (int j = 0; j < 64; j++) o = fmaf(hid[j], fc2w[j * C_CLASSES + t], o);
        out[g * C_CLASSES + t] = o;
    }
}

__global__ void tail_kernel(float* __restrict__ out, int out_size) {
    int i = G_GRAPHS * C_CLASSES + blockIdx.x * blockDim.x + threadIdx.x;
    if (i < out_size) out[i] = 0.f;
}

// ---------------- launcher ----------------
extern "C" void kernel_launch(void* const* d_in, const int* in_sizes, int n_in,
                              void* d_out, int out_size)
{
    const float* x      = (const float*)d_in[0];
    const int*   ei     = (const int*)d_in[1];
    const int*   batch  = (const int*)d_in[2];
    const float* w_in   = (const float*)d_in[3];
    const float* b_in   = (const float*)d_in[4];
    const float* conv_w = (const float*)d_in[5];
    const float* conv_b = (const float*)d_in[6];
    const float* bn_g   = (const float*)d_in[7];
    const float* bn_b   = (const float*)d_in[8];
    const float* bn_m   = (const float*)d_in[9];
    const float* bn_v   = (const float*)d_in[10];
    const float* fc1w   = (const float*)d_in[11];
    const float* fc1b   = (const float*)d_in[12];
    const float* fc2w   = (const float*)d_in[13];
    const float* fc2b   = (const float*)d_in[14];
    float*       out    = (float*)d_out;

    const int SMEM = (128 * W_STRIDE + 64 * A_STRIDE) * 4;   // 103424 B
    cudaFuncSetAttribute(gemm_kernel, cudaFuncAttributeMaxDynamicSharedMemorySize, SMEM);

    zero_kernel    <<<(N_NODES + 255) / 256, 256>>>();
    degree_kernel  <<<(E_EDGES + 255) / 256, 256>>>(ei);
    scan_kernel    <<<1, SCAN_T>>>();
    fill_csr_kernel<<<(E_EDGES + 255) / 256, 256>>>(ei);

    // input projection
    gemm_kernel<<<(N_NODES + 63) / 64, 256, SMEM>>>(x, w_in, b_in, 0);

    const unsigned node_warp_blocks = ((unsigned)N_NODES * 32u + 255) / 256;

    for (int l = 0; l < L_LAYERS; l++) {
        gemm_kernel<<<(N_NODES + 63) / 64, 256, SMEM>>>(nullptr, conv_w + (size_t)l * 128 * 128, nullptr, 1);
        agg_kernel <<<node_warp_blocks, 256>>>(conv_b + l * 128,
                                               bn_g + l * 128, bn_b + l * 128,
                                               bn_m + l * 128, bn_v + l * 128,
                                               batch, (l == L_LAYERS - 1) ? 1 : 0);
    }

    mlp_kernel<<<G_GRAPHS, 64>>>(fc1w, fc1b, fc2w, fc2b, out);

    int tail = out_size - G_GRAPHS * C_CLASSES;
    if (tail > 0) tail_kernel<<<(tail + 255) / 256, 256>>>(out, out_size);
}